// round 6
// baseline (speedup 1.0000x reference)
#include <cuda_runtime.h>

#define NN    131072
#define KK    27
#define FINN  3
#define FOUTN 32
#define EPSB  1e-5f

#define TILE2   256   // nodes per stage2 block (1 node/thread)
#define THR2    256
#define RSTRIDE 36    // staging row stride in floats (144B: conflict-free LDS.128)
#define STGF    (TILE2 * RSTRIDE)   // 9216 floats per stage buffer

// Scratch: h [N,32] fp32 (16MB); x padded to 16B rows (2MB)
__device__ __align__(256) float g_h[NN * FOUTN];
__device__ __align__(256) float g_x4[NN * 4];

typedef unsigned long long ull;

__device__ __forceinline__ ull fma2(ull a, ull b, ull c) {
    ull d;
    asm("fma.rn.f32x2 %0, %1, %2, %3;" : "=l"(d) : "l"(a), "l"(b), "l"(c));
    return d;
}
__device__ __forceinline__ ull pack2(float x) {
    ull r; unsigned u = __float_as_uint(x);
    asm("mov.b64 %0, {%1, %2};" : "=l"(r) : "r"(u), "r"(u));
    return r;
}
__device__ __forceinline__ float2 unpack2(ull v) {
    unsigned lo, hi;
    asm("mov.b64 {%0, %1}, %2;" : "=r"(lo), "=r"(hi) : "l"(v));
    return make_float2(__uint_as_float(lo), __uint_as_float(hi));
}
__device__ __forceinline__ void cpa16(unsigned s, const void* g) {
    asm volatile("cp.async.ca.shared.global [%0], [%1], 16;" :: "r"(s), "l"(g));
}
__device__ __forceinline__ void cpa_commit() {
    asm volatile("cp.async.commit_group;" ::: "memory");
}

// ============================================================================
// Repack x_feats [N,3] -> g_x4 [N,4]: stage1 gather becomes one LDG.128/row
// ============================================================================
__global__ __launch_bounds__(256)
void repack_kernel(const float* __restrict__ x_feats) {
    const int n = blockIdx.x * blockDim.x + threadIdx.x;
    const float* s = x_feats + (size_t)n * 3;
    ((float4*)g_x4)[n] = make_float4(s[0], s[1], s[2], 0.f);
}

// ============================================================================
// Stage 1: h[n,:] = silu(bn1( sum_k sum_f x4[nbr[n,k]].f * w1[k,f,:] ))
// ============================================================================
__global__ __launch_bounds__(256)
void stage1_kernel(const int*   __restrict__ nbr,
                   const float* __restrict__ w1,
                   const float* __restrict__ gamma1,
                   const float* __restrict__ beta1,
                   const float* __restrict__ mean1,
                   const float* __restrict__ var1)
{
    __shared__ __align__(16) float w1s[KK * FINN * FOUTN];
    __shared__ float s_scale[FOUTN], s_shift[FOUTN];

    const int tid = threadIdx.x;
    for (int i = tid; i < (KK * FINN * FOUTN) / 4; i += blockDim.x)
        ((float4*)w1s)[i] = ((const float4*)w1)[i];
    if (tid < FOUTN) {
        float sc = gamma1[tid] * rsqrtf(var1[tid] + EPSB);
        s_scale[tid] = sc;
        s_shift[tid] = beta1[tid] - mean1[tid] * sc;
    }
    __syncthreads();

    const int n = blockIdx.x * blockDim.x + tid;
    const int* nrow = nbr + (size_t)n * KK;

    ull acc[16];
    #pragma unroll
    for (int i = 0; i < 16; i++) acc[i] = 0ULL;

    int idx_next = nrow[0];
    #pragma unroll 1
    for (int k = 0; k < KK; k++) {
        const int idx = idx_next;
        if (k + 1 < KK) idx_next = nrow[k + 1];
        float4 xv4 = ((const float4*)g_x4)[idx];
        float xv[3] = {xv4.x, xv4.y, xv4.z};
        #pragma unroll
        for (int f = 0; f < FINN; f++) {
            ull s2 = pack2(xv[f]);
            const ulonglong2* wp = (const ulonglong2*)(w1s + (k * FINN + f) * FOUTN);
            #pragma unroll
            for (int j = 0; j < 8; j++) {
                ulonglong2 w = wp[j];
                acc[2 * j]     = fma2(s2, w.x, acc[2 * j]);
                acc[2 * j + 1] = fma2(s2, w.y, acc[2 * j + 1]);
            }
        }
    }

    float outv[FOUTN];
    #pragma unroll
    for (int i = 0; i < 16; i++) {
        float2 v = unpack2(acc[i]);
        outv[2 * i] = v.x; outv[2 * i + 1] = v.y;
    }
    float4* dst = (float4*)(g_h + (size_t)n * FOUTN);
    #pragma unroll
    for (int j = 0; j < 8; j++) {
        float4 o4; float v;
        v = outv[4*j+0] * s_scale[4*j+0] + s_shift[4*j+0]; o4.x = v / (1.f + __expf(-v));
        v = outv[4*j+1] * s_scale[4*j+1] + s_shift[4*j+1]; o4.y = v / (1.f + __expf(-v));
        v = outv[4*j+2] * s_scale[4*j+2] + s_shift[4*j+2]; o4.z = v / (1.f + __expf(-v));
        v = outv[4*j+3] * s_scale[4*j+3] + s_shift[4*j+3]; o4.w = v / (1.f + __expf(-v));
        dst[j] = o4;
    }
}

// ============================================================================
// Stage 2: x_out[n,:] = sum_k h[nbr[n,k],:] @ w2[k,:,:]; fuse point branch.
// 256 thr x 1 node; cp.async double-buffered gather (8 lanes/row) AND
// per-k w2 streaming (4KB) -> ~84KB smem -> 2 CTAs/SM.
// ============================================================================
// smem floats: stage 2*9216, w2buf 2*1024, idx 2*256 ints, zw 96, zb 32
#define SMEM2_FLOATS (2 * STGF + 2 * 1024 + 512 + 96 + 32)
#define SMEM2_BYTES  (SMEM2_FLOATS * 4)

__global__ __launch_bounds__(THR2, 2)
void stage2_kernel(const float* __restrict__ z_feats,
                   const int*   __restrict__ nbr,
                   const float* __restrict__ w2,
                   const float* __restrict__ mlp_w,
                   const float* __restrict__ mlp_b,
                   const float* __restrict__ mlp_gamma,
                   const float* __restrict__ mlp_beta,
                   const float* __restrict__ mlp_mean,
                   const float* __restrict__ mlp_var,
                   float* __restrict__ out,
                   int N, int copies)
{
    extern __shared__ __align__(16) float sm[];
    float* stg[2]  = { sm, sm + STGF };
    float* w2b[2]  = { sm + 2 * STGF, sm + 2 * STGF + 1024 };
    int*   idxb    = (int*)(sm + 2 * STGF + 2048);   // [2][256]
    float* zw      = (float*)(idxb + 512);           // 96
    float* zb      = zw + 96;                        // 32

    const unsigned stg_u[2]  = { (unsigned)__cvta_generic_to_shared(stg[0]),
                                 (unsigned)__cvta_generic_to_shared(stg[1]) };
    const unsigned w2b_u[2]  = { (unsigned)__cvta_generic_to_shared(w2b[0]),
                                 (unsigned)__cvta_generic_to_shared(w2b[1]) };

    const int t = threadIdx.x;
    const int node = blockIdx.x * TILE2 + t;
    const int* nr = nbr + (size_t)node * KK;

    if (t < FOUTN) {
        float sc = mlp_gamma[t] * rsqrtf(mlp_var[t] + EPSB);
        float sh = mlp_beta[t] - mlp_mean[t] * sc;
        zb[t] = mlp_b[t] * sc + sh;
        #pragma unroll
        for (int f = 0; f < FINN; f++)
            zw[f * FOUTN + t] = mlp_w[f * FOUTN + t] * sc;
    }

    // prologue: idx for k=0 (buf0) and k=1 (buf1)
    idxb[t]       = nr[0];
    idxb[256 + t] = nr[1];
    __syncthreads();

    // issue k=0 gather + w2 into buf0
    {
        const int g = t & 7;            // 16B segment within row
        const int rb = t >> 3;          // row base
        #pragma unroll
        for (int p = 0; p < 8; p++) {
            int r = p * 32 + rb;
            int idx = idxb[r];
            cpa16(stg_u[0] + (unsigned)(r * RSTRIDE + g * 4) * 4u,
                  g_h + (size_t)idx * FOUTN + g * 4);
        }
        cpa16(w2b_u[0] + (unsigned)t * 16u, w2 + t * 4);
        cpa_commit();
    }

    ull acc[16];
    #pragma unroll
    for (int i = 0; i < 16; i++) acc[i] = 0ULL;

    const int g  = t & 7;
    const int rb = t >> 3;

    #pragma unroll 1
    for (int k = 0; k < KK; k++) {
        const int cur = k & 1;
        // issue k+1 into the other buffer
        if (k + 1 < KK) {
            const int nb = (k + 1) & 1;
            const int* ib = idxb + nb * 256;
            #pragma unroll
            for (int p = 0; p < 8; p++) {
                int r = p * 32 + rb;
                int idx = ib[r];
                cpa16(stg_u[nb] + (unsigned)(r * RSTRIDE + g * 4) * 4u,
                      g_h + (size_t)idx * FOUTN + g * 4);
            }
            cpa16(w2b_u[nb] + (unsigned)t * 16u, w2 + (k + 1) * 1024 + t * 4);
            cpa_commit();
        }
        int nxt = 0;
        if (k + 2 < KK) nxt = nr[k + 2];

        if (k + 1 < KK) asm volatile("cp.async.wait_group 1;" ::: "memory");
        else            asm volatile("cp.async.wait_group 0;" ::: "memory");
        __syncthreads();   // buf[cur] (rows + w2) visible

        // compute k
        const float* myrow = stg[cur] + t * RSTRIDE;
        float hv[FOUTN];
        #pragma unroll
        for (int j = 0; j < 8; j++) {
            float4 x4 = *(const float4*)(myrow + j * 4);
            hv[4*j+0] = x4.x; hv[4*j+1] = x4.y; hv[4*j+2] = x4.z; hv[4*j+3] = x4.w;
        }
        const float* wk = w2b[cur];
        #pragma unroll
        for (int f = 0; f < FOUTN; f++) {
            ull s2 = pack2(hv[f]);
            const ulonglong2* wp = (const ulonglong2*)(wk + f * FOUTN);
            #pragma unroll
            for (int j = 0; j < 8; j++) {
                ulonglong2 w = wp[j];
                acc[2*j]   = fma2(s2, w.x, acc[2*j]);
                acc[2*j+1] = fma2(s2, w.y, acc[2*j+1]);
            }
        }

        // stage idx for k+2 into buf[cur] (its k-indices were consumed at iter k-1)
        if (k + 2 < KK) idxb[cur * 256 + t] = nxt;
        __syncthreads();   // compute-readers done with buf[cur]; idx visible
    }

    // epilogue: point branch + writeout
    const float* zr = z_feats + (size_t)node * FINN;
    float z0 = zr[0], z1 = zr[1], z2 = zr[2];

    float outv[FOUTN];
    #pragma unroll
    for (int i = 0; i < 16; i++) {
        float2 v = unpack2(acc[i]);
        outv[2*i] = v.x; outv[2*i+1] = v.y;
    }
    #pragma unroll
    for (int o = 0; o < FOUTN; o++) {
        float zp = z0 * zw[o] + z1 * zw[FOUTN + o] + z2 * zw[2*FOUTN + o] + zb[o];
        outv[o] += fmaxf(zp, 0.f);
    }
    float4* dst0 = (float4*)(out + (size_t)node * FOUTN);
    #pragma unroll
    for (int j = 0; j < 8; j++)
        dst0[j] = make_float4(outv[4*j], outv[4*j+1], outv[4*j+2], outv[4*j+3]);
    if (copies > 1) {
        float4* dst1 = (float4*)(out + (size_t)N * FOUTN + (size_t)node * FOUTN);
        #pragma unroll
        for (int j = 0; j < 8; j++)
            dst1[j] = make_float4(outv[4*j], outv[4*j+1], outv[4*j+2], outv[4*j+3]);
    }
}

extern "C" void kernel_launch(void* const* d_in, const int* in_sizes, int n_in,
                              void* d_out, int out_size) {
    const float* x_feats   = (const float*)d_in[0];
    const float* z_feats   = (const float*)d_in[1];
    const int*   nbr       = (const int*)d_in[2];
    const float* w1        = (const float*)d_in[3];
    const float* bn1_gamma = (const float*)d_in[4];
    const float* bn1_beta  = (const float*)d_in[5];
    const float* bn1_mean  = (const float*)d_in[6];
    const float* bn1_var   = (const float*)d_in[7];
    const float* w2        = (const float*)d_in[8];
    const float* mlp_w     = (const float*)d_in[9];
    const float* mlp_b     = (const float*)d_in[10];
    const float* mlp_gamma = (const float*)d_in[11];
    const float* mlp_beta  = (const float*)d_in[12];
    const float* mlp_mean  = (const float*)d_in[13];
    const float* mlp_var   = (const float*)d_in[14];

    const int N = in_sizes[0] / FINN;
    const int copies = out_size / (N * FOUTN);

    static int cfg_done = 0;
    if (!cfg_done) {
        (void)cudaFuncSetAttribute(stage2_kernel,
                                   cudaFuncAttributeMaxDynamicSharedMemorySize,
                                   SMEM2_BYTES);
        cfg_done = 1;
    }

    repack_kernel<<<N / 256, 256>>>(x_feats);
    stage1_kernel<<<N / 256, 256>>>(nbr, w1, bn1_gamma, bn1_beta, bn1_mean, bn1_var);
    stage2_kernel<<<N / TILE2, THR2, SMEM2_BYTES>>>(z_feats, nbr, w2,
                                                    mlp_w, mlp_b, mlp_gamma, mlp_beta,
                                                    mlp_mean, mlp_var,
                                                    (float*)d_out, N, copies);
}

// round 7
// speedup vs baseline: 1.5599x; 1.5599x over previous
#include <cuda_runtime.h>

#define NN    131072
#define KK    27
#define FINN  3
#define FOUTN 32
#define EPSB  1e-5f

#define THR2    128   // threads per stage2 block
#define TILE2   256   // nodes per stage2 block (2 nodes/thread)
#define RSTRIDE 36    // staging row stride in floats (144B: conflict-free LDS.128)
#define STGF    (TILE2 * RSTRIDE)   // 9216 floats per stage buffer

// Scratch: h [N,32] fp32 (16MB); x padded to 16B rows (2MB)
__device__ __align__(256) float g_h[NN * FOUTN];
__device__ __align__(256) float g_x4[NN * 4];

typedef unsigned long long ull;

__device__ __forceinline__ ull fma2(ull a, ull b, ull c) {
    ull d;
    asm("fma.rn.f32x2 %0, %1, %2, %3;" : "=l"(d) : "l"(a), "l"(b), "l"(c));
    return d;
}
__device__ __forceinline__ ull pack2(float x) {
    ull r; unsigned u = __float_as_uint(x);
    asm("mov.b64 %0, {%1, %2};" : "=l"(r) : "r"(u), "r"(u));
    return r;
}
__device__ __forceinline__ float2 unpack2(ull v) {
    unsigned lo, hi;
    asm("mov.b64 {%0, %1}, %2;" : "=r"(lo), "=r"(hi) : "l"(v));
    return make_float2(__uint_as_float(lo), __uint_as_float(hi));
}
__device__ __forceinline__ void cpa16(unsigned s, const void* g) {
    asm volatile("cp.async.ca.shared.global [%0], [%1], 16;" :: "r"(s), "l"(g));
}
__device__ __forceinline__ void cpa_commit() {
    asm volatile("cp.async.commit_group;" ::: "memory");
}

// ============================================================================
// Repack x_feats [N,3] -> g_x4 [N,4]: stage1 gather becomes one LDG.128/row
// ============================================================================
__global__ __launch_bounds__(256)
void repack_kernel(const float* __restrict__ x_feats) {
    const int n = blockIdx.x * blockDim.x + threadIdx.x;
    const float* s = x_feats + (size_t)n * 3;
    ((float4*)g_x4)[n] = make_float4(s[0], s[1], s[2], 0.f);
}

// ============================================================================
// Stage 1: h[n,:] = silu(bn1( sum_k sum_f x4[nbr[n,k]].f * w1[k,f,:] ))
// ============================================================================
__global__ __launch_bounds__(256)
void stage1_kernel(const int*   __restrict__ nbr,
                   const float* __restrict__ w1,
                   const float* __restrict__ gamma1,
                   const float* __restrict__ beta1,
                   const float* __restrict__ mean1,
                   const float* __restrict__ var1)
{
    __shared__ __align__(16) float w1s[KK * FINN * FOUTN];
    __shared__ float s_scale[FOUTN], s_shift[FOUTN];

    const int tid = threadIdx.x;
    for (int i = tid; i < (KK * FINN * FOUTN) / 4; i += blockDim.x)
        ((float4*)w1s)[i] = ((const float4*)w1)[i];
    if (tid < FOUTN) {
        float sc = gamma1[tid] * rsqrtf(var1[tid] + EPSB);
        s_scale[tid] = sc;
        s_shift[tid] = beta1[tid] - mean1[tid] * sc;
    }
    __syncthreads();

    const int n = blockIdx.x * blockDim.x + tid;
    const int* nrow = nbr + (size_t)n * KK;

    ull acc[16];
    #pragma unroll
    for (int i = 0; i < 16; i++) acc[i] = 0ULL;

    int idx_next = nrow[0];
    #pragma unroll 1
    for (int k = 0; k < KK; k++) {
        const int idx = idx_next;
        if (k + 1 < KK) idx_next = nrow[k + 1];
        float4 xv4 = ((const float4*)g_x4)[idx];
        float xv[3] = {xv4.x, xv4.y, xv4.z};
        #pragma unroll
        for (int f = 0; f < FINN; f++) {
            ull s2 = pack2(xv[f]);
            const ulonglong2* wp = (const ulonglong2*)(w1s + (k * FINN + f) * FOUTN);
            #pragma unroll
            for (int j = 0; j < 8; j++) {
                ulonglong2 w = wp[j];
                acc[2 * j]     = fma2(s2, w.x, acc[2 * j]);
                acc[2 * j + 1] = fma2(s2, w.y, acc[2 * j + 1]);
            }
        }
    }

    float outv[FOUTN];
    #pragma unroll
    for (int i = 0; i < 16; i++) {
        float2 v = unpack2(acc[i]);
        outv[2 * i] = v.x; outv[2 * i + 1] = v.y;
    }
    float4* dst = (float4*)(g_h + (size_t)n * FOUTN);
    #pragma unroll
    for (int j = 0; j < 8; j++) {
        float4 o4; float v;
        v = outv[4*j+0] * s_scale[4*j+0] + s_shift[4*j+0]; o4.x = v / (1.f + __expf(-v));
        v = outv[4*j+1] * s_scale[4*j+1] + s_shift[4*j+1]; o4.y = v / (1.f + __expf(-v));
        v = outv[4*j+2] * s_scale[4*j+2] + s_shift[4*j+2]; o4.z = v / (1.f + __expf(-v));
        v = outv[4*j+3] * s_scale[4*j+3] + s_shift[4*j+3]; o4.w = v / (1.f + __expf(-v));
        dst[j] = o4;
    }
}

// ============================================================================
// Stage 2: x_out[n,:] = sum_k h[nbr[n,k],:] @ w2[k,:,:]; fuse point branch.
// 128 thr x 2 nodes (TILE 256); cp.async double-buffered gather + per-k w2
// stream; ~84KB smem -> 2 CTAs/SM; each w2 LDS feeds 2 nodes (fma:LDS ~4:1).
// ============================================================================
// smem floats: stage 2*9216, w2buf 2*1024, idx 2*256 ints, zw 96, zb 32
#define SMEM2_FLOATS (2 * STGF + 2 * 1024 + 512 + 96 + 32)
#define SMEM2_BYTES  (SMEM2_FLOATS * 4)

__global__ __launch_bounds__(THR2, 2)
void stage2_kernel(const float* __restrict__ z_feats,
                   const int*   __restrict__ nbr,
                   const float* __restrict__ w2,
                   const float* __restrict__ mlp_w,
                   const float* __restrict__ mlp_b,
                   const float* __restrict__ mlp_gamma,
                   const float* __restrict__ mlp_beta,
                   const float* __restrict__ mlp_mean,
                   const float* __restrict__ mlp_var,
                   float* __restrict__ out,
                   int N, int copies)
{
    extern __shared__ __align__(16) float sm[];
    float* stg[2]  = { sm, sm + STGF };
    float* w2b[2]  = { sm + 2 * STGF, sm + 2 * STGF + 1024 };
    int*   idxb    = (int*)(sm + 2 * STGF + 2048);   // [2][256]
    float* zw      = (float*)(idxb + 512);           // 96
    float* zb      = zw + 96;                        // 32

    const unsigned stg_u[2] = { (unsigned)__cvta_generic_to_shared(stg[0]),
                                (unsigned)__cvta_generic_to_shared(stg[1]) };
    const unsigned w2b_u[2] = { (unsigned)__cvta_generic_to_shared(w2b[0]),
                                (unsigned)__cvta_generic_to_shared(w2b[1]) };

    const int t = threadIdx.x;
    const int base  = blockIdx.x * TILE2;
    const int node0 = base + t;
    const int node1 = base + THR2 + t;
    const int* nr0 = nbr + (size_t)node0 * KK;
    const int* nr1 = nbr + (size_t)node1 * KK;

    if (t < FOUTN) {
        float sc = mlp_gamma[t] * rsqrtf(mlp_var[t] + EPSB);
        float sh = mlp_beta[t] - mlp_mean[t] * sc;
        zb[t] = mlp_b[t] * sc + sh;
        #pragma unroll
        for (int f = 0; f < FINN; f++)
            zw[f * FOUTN + t] = mlp_w[f * FOUTN + t] * sc;
    }

    // prologue: idx for k=0 (buf0) and k=1 (buf1)
    idxb[t]             = nr0[0];
    idxb[THR2 + t]      = nr1[0];
    idxb[256 + t]       = nr0[1];
    idxb[256 + THR2 + t] = nr1[1];
    __syncthreads();

    // issue k=0 gather (16 segs/thread) + w2 (8 floats/thread) into buf0
    {
        #pragma unroll
        for (int p = 0; p < 16; p++) {
            int s = p * THR2 + t; int r = s >> 3; int g = s & 7;
            cpa16(stg_u[0] + (unsigned)(r * RSTRIDE + g * 4) * 4u,
                  g_h + (size_t)idxb[r] * FOUTN + g * 4);
        }
        cpa16(w2b_u[0] + (unsigned)t * 32u,       w2 + t * 8);
        cpa16(w2b_u[0] + (unsigned)t * 32u + 16u, w2 + t * 8 + 4);
        cpa_commit();
    }

    ull acc0[16], acc1[16];
    #pragma unroll
    for (int i = 0; i < 16; i++) { acc0[i] = 0ULL; acc1[i] = 0ULL; }

    #pragma unroll 1
    for (int k = 0; k < KK; k++) {
        const int cur = k & 1;
        // issue k+1 into the other buffer
        if (k + 1 < KK) {
            const int nb = (k + 1) & 1;
            const int* ib = idxb + nb * 256;
            #pragma unroll
            for (int p = 0; p < 16; p++) {
                int s = p * THR2 + t; int r = s >> 3; int g = s & 7;
                cpa16(stg_u[nb] + (unsigned)(r * RSTRIDE + g * 4) * 4u,
                      g_h + (size_t)ib[r] * FOUTN + g * 4);
            }
            const float* wsrc = w2 + (k + 1) * 1024;
            cpa16(w2b_u[nb] + (unsigned)t * 32u,       wsrc + t * 8);
            cpa16(w2b_u[nb] + (unsigned)t * 32u + 16u, wsrc + t * 8 + 4);
            cpa_commit();
        }
        int nxt0 = 0, nxt1 = 0;
        if (k + 2 < KK) { nxt0 = nr0[k + 2]; nxt1 = nr1[k + 2]; }

        if (k + 1 < KK) asm volatile("cp.async.wait_group 1;" ::: "memory");
        else            asm volatile("cp.async.wait_group 0;" ::: "memory");
        __syncthreads();   // buf[cur] (rows + w2) visible

        // compute k: both nodes share every w2 LDS
        const float* myrow0 = stg[cur] + t * RSTRIDE;
        const float* myrow1 = stg[cur] + (THR2 + t) * RSTRIDE;
        const float* wk = w2b[cur];
        #pragma unroll
        for (int c = 0; c < 4; c++) {
            float4 a0 = *(const float4*)(myrow0 + c * 8);
            float4 b0 = *(const float4*)(myrow0 + c * 8 + 4);
            float4 a1 = *(const float4*)(myrow1 + c * 8);
            float4 b1 = *(const float4*)(myrow1 + c * 8 + 4);
            float h0v[8] = {a0.x, a0.y, a0.z, a0.w, b0.x, b0.y, b0.z, b0.w};
            float h1v[8] = {a1.x, a1.y, a1.z, a1.w, b1.x, b1.y, b1.z, b1.w};
            #pragma unroll
            for (int ff = 0; ff < 8; ff++) {
                int f = c * 8 + ff;
                ull s0 = pack2(h0v[ff]);
                ull s1 = pack2(h1v[ff]);
                const ulonglong2* wp = (const ulonglong2*)(wk + f * FOUTN);
                #pragma unroll
                for (int j = 0; j < 8; j++) {
                    ulonglong2 w = wp[j];
                    acc0[2*j]   = fma2(s0, w.x, acc0[2*j]);
                    acc0[2*j+1] = fma2(s0, w.y, acc0[2*j+1]);
                    acc1[2*j]   = fma2(s1, w.x, acc1[2*j]);
                    acc1[2*j+1] = fma2(s1, w.y, acc1[2*j+1]);
                }
            }
        }

        // stage idx for k+2 into buf[cur] (its k-indices already consumed)
        if (k + 2 < KK) {
            int* ob = idxb + cur * 256;
            ob[t] = nxt0; ob[THR2 + t] = nxt1;
        }
        __syncthreads();   // readers done with buf[cur]; idx visible
    }

    // epilogue: point branch + writeout, both nodes
    #pragma unroll
    for (int which = 0; which < 2; which++) {
        const int n = which ? node1 : node0;
        ull* acc = which ? acc1 : acc0;
        const float* zr = z_feats + (size_t)n * FINN;
        float z0 = zr[0], z1 = zr[1], z2 = zr[2];

        float outv[FOUTN];
        #pragma unroll
        for (int i = 0; i < 16; i++) {
            float2 v = unpack2(acc[i]);
            outv[2*i] = v.x; outv[2*i+1] = v.y;
        }
        #pragma unroll
        for (int o = 0; o < FOUTN; o++) {
            float zp = z0 * zw[o] + z1 * zw[FOUTN + o] + z2 * zw[2*FOUTN + o] + zb[o];
            outv[o] += fmaxf(zp, 0.f);
        }
        float4* dst0 = (float4*)(out + (size_t)n * FOUTN);
        #pragma unroll
        for (int j = 0; j < 8; j++)
            dst0[j] = make_float4(outv[4*j], outv[4*j+1], outv[4*j+2], outv[4*j+3]);
        if (copies > 1) {
            float4* dst1 = (float4*)(out + (size_t)N * FOUTN + (size_t)n * FOUTN);
            #pragma unroll
            for (int j = 0; j < 8; j++)
                dst1[j] = make_float4(outv[4*j], outv[4*j+1], outv[4*j+2], outv[4*j+3]);
        }
    }
}

extern "C" void kernel_launch(void* const* d_in, const int* in_sizes, int n_in,
                              void* d_out, int out_size) {
    const float* x_feats   = (const float*)d_in[0];
    const float* z_feats   = (const float*)d_in[1];
    const int*   nbr       = (const int*)d_in[2];
    const float* w1        = (const float*)d_in[3];
    const float* bn1_gamma = (const float*)d_in[4];
    const float* bn1_beta  = (const float*)d_in[5];
    const float* bn1_mean  = (const float*)d_in[6];
    const float* bn1_var   = (const float*)d_in[7];
    const float* w2        = (const float*)d_in[8];
    const float* mlp_w     = (const float*)d_in[9];
    const float* mlp_b     = (const float*)d_in[10];
    const float* mlp_gamma = (const float*)d_in[11];
    const float* mlp_beta  = (const float*)d_in[12];
    const float* mlp_mean  = (const float*)d_in[13];
    const float* mlp_var   = (const float*)d_in[14];

    const int N = in_sizes[0] / FINN;
    const int copies = out_size / (N * FOUTN);

    static int cfg_done = 0;
    if (!cfg_done) {
        (void)cudaFuncSetAttribute(stage2_kernel,
                                   cudaFuncAttributeMaxDynamicSharedMemorySize,
                                   SMEM2_BYTES);
        cfg_done = 1;
    }

    repack_kernel<<<N / 256, 256>>>(x_feats);
    stage1_kernel<<<N / 256, 256>>>(nbr, w1, bn1_gamma, bn1_beta, bn1_mean, bn1_var);
    stage2_kernel<<<N / TILE2, THR2, SMEM2_BYTES>>>(z_feats, nbr, w2,
                                                    mlp_w, mlp_b, mlp_gamma, mlp_beta,
                                                    mlp_mean, mlp_var,
                                                    (float*)d_out, N, copies);
}